// round 9
// baseline (speedup 1.0000x reference)
#include <cuda_runtime.h>
#include <cuda_bf16.h>
#include <cstdint>

// Problem constants (from reference)
#define BATCH 512
#define CH    12
#define TLEN  4096
#define TD    1024     // TLEN / 4 (downsampled)
#define KS    51
#define STEPS 7
#define NTHR  512
#define ROWN  (CH * TLEN)          // 49152 floats per row

// Dynamic smem partition (floats):
//   s_src : [0, 49152)                  full source row (192 KB)
//   s_vec : [49152, 49152+1056)         padded downsampled field (uses 1044)
//   s_buf : [50208, 50208+2048)         ping-pong integration buffers
//   s_flow: [50208, 50208+4096)         full-res flow (aliases s_buf; buf is
//                                       dead before flow is written)
#define OFF_VEC  49152
#define OFF_BUF  (49152 + 1056)
#define SMEM_FLOATS (OFF_BUF + 4096)
#define SMEM_BYTES  (SMEM_FLOATS * 4)    // 217216 B

__global__ __launch_bounds__(NTHR, 1)
void k_fused(const float* __restrict__ src,
             const float* __restrict__ noise,
             const float* __restrict__ flow_mag,
             const float* __restrict__ sker,
             float* __restrict__ out) {
    extern __shared__ float smem[];
    float* s_src  = smem;
    float* s_vec  = smem + OFF_VEC;      // [8 zeros][4*vec 1024][9 zeros]
    float* s_buf  = smem + OFF_BUF;      // buf[cur*1024 + q]
    float* s_flow = smem + OFF_BUF;      // aliases s_buf (phase 2)

    __shared__ float ker_s[52];
    __shared__ __align__(16) float h4_s[16 * 4];  // h4_s[k*4+r] = h[r][k-7]

    const int b   = blockIdx.x;
    const int tid = threadIdx.x;
    const float mag = flow_mag[0];
    const float INV_TD1 = 1.0f / (float)(TD - 1);

    // ---- 1. kick off the bulk source-row prefetch (global -> shared),
    //         fully asynchronous; integration runs in its shadow.
    {
        uint32_t sa = (uint32_t)__cvta_generic_to_shared(s_src);
        const char* ga = (const char*)(src + (size_t)b * ROWN);
        #pragma unroll
        for (int k = 0; k < 24; ++k) {
            int off = (tid + NTHR * k) * 16;     // 24*512*16 = 196608 B
            asm volatile("cp.async.cg.shared.global [%0], [%1], 16;"
                         :: "r"(sa + off), "l"(ga + off));
        }
        asm volatile("cp.async.commit_group;");
    }

    // ---- 2. init: resize_linear(flow_field, 0.25) -> src = 4q+1.5,
    //         i0 = 4q+1, w = 0.5 ; resize_transform(<1): *0.25 ; VecInt /2^7
    float f[2];
    {
        const float* nrow = noise + (size_t)b * TLEN;
        #pragma unroll
        for (int j = 0; j < 2; ++j) {
            int q = tid + NTHR * j;
            float n0 = nrow[4 * q + 1];
            float n1 = nrow[4 * q + 2];
            float pf = 0.25f * ((mag * n0) * 0.5f + (mag * n1) * 0.5f);
            f[j] = pf * (1.0f / 128.0f);
            s_buf[q] = f[j];
        }
    }
    if (tid < 51) ker_s[tid] = sker[tid];
    if (tid < 8)  s_vec[tid] = 0.0f;
    if (tid < 9)  s_vec[1032 + tid] = 0.0f;
    __syncthreads();

    // ---- 3. composite polyphase kernel h[r][m], m = k-7 in [-7,8]
    //         flow[4q+r] = sum_m h[r][m] * (4*vec[q+m])   (interior)
    if (tid < 64) {
        const int r = tid >> 4;
        const int k = tid & 15;
        const int m = k - 7;
        const float W[4] = {0.625f, 0.875f, 0.125f, 0.375f};
        float acc = 0.0f;
        for (int j = -25; j <= 25; ++j) {
            int srp = r + j + 100;            // sr + 100, 100 % 4 == 0
            int p   = srp / 4 - 25;           // floor_div(sr, 4)
            int rho = srp & 3;
            int d   = (rho >= 2) ? 0 : -1;
            float w = W[rho];
            float g = ker_s[j + 25];
            int tgt = p + d;
            if (tgt == m)     acc += g * (1.0f - w);
            if (tgt + 1 == m) acc += g * w;
        }
        h4_s[k * 4 + r] = acc;
    }
    __syncthreads();

    // ---- 4. VecInt: 7 scaling-and-squaring warp steps (exact R8 fp sequence)
    int cur = 0;
    #pragma unroll
    for (int it = 0; it < STEPS; ++it) {
        const float* bc = s_buf + cur * TD;
        float* bn = s_buf + (1 - cur) * TD;
        #pragma unroll
        for (int j = 0; j < 2; ++j) {
            int q = tid + NTHR * j;
            float nl = (float)q + f[j];

            float ixn = nl * INV_TD1;
            float xw = fminf(fminf(ixn + 1.0f, 2.0f - ixn), 1.0f);
            xw = fmaxf(xw, 0.0f);

            float y0 = floorf(nl);
            float fy = nl - y0;
            int y0i = (int)y0;
            int y1i = y0i + 1;
            float m0 = (y0i >= 0 && y0i < TD) ? 1.0f : 0.0f;
            float m1 = (y1i >= 0 && y1i < TD) ? 1.0f : 0.0f;
            int y0c = min(max(y0i, 0), TD - 1);
            int y1c = min(max(y1i, 0), TD - 1);
            float g0 = bc[y0c];
            float g1 = bc[y1c];
            float warped = xw * ((1.0f - fy) * (m0 * g0) + fy * (m1 * g1));
            f[j] = f[j] + warped;
            bn[q] = f[j];
        }
        cur ^= 1;
        __syncthreads();
    }

    // ---- 5. publish scaled field (resize_transform >1: magnitude x4)
    #pragma unroll
    for (int j = 0; j < 2; ++j)
        s_vec[8 + tid + NTHR * j] = 4.0f * f[j];
    __syncthreads();      // after this, s_buf is dead -> s_flow may overwrite

    // ---- 6. 15-tap polyphase conv -> s_flow (full-res smoothed flow)
    {
        const float4* h4 = reinterpret_cast<const float4*>(h4_s);
        float v0 = s_vec[8];
        float vL = s_vec[8 + 1023];
        #pragma unroll
        for (int j = 0; j < 2; ++j) {
            int q = tid + NTHR * j;
            const float* wnd = s_vec + q + 1;  // vec[q-7 .. q+8] (zero-padded)
            float a0 = 0.f, a1 = 0.f, a2 = 0.f, a3 = 0.f;
            #pragma unroll
            for (int k = 0; k < 16; ++k) {
                float wv = wnd[k];
                float4 hk = h4[k];
                a0 += hk.x * wv;
                a1 += hk.y * wv;
                a2 += hk.z * wv;
                a3 += hk.w * wv;
            }
            // Boundary corrections (R7 derivation): polyphase interior formula
            // with zero-padded vec differs from the reference's clamped
            // upsample + zero-padded conv at exactly 8 upsampled sites.
            if (q < 7 || q >= 1017) {
                auto G = [&](int jj) -> float {
                    return (jj >= -25 && jj <= 25) ? ker_s[jj + 25] : 0.0f;
                };
                auto corr = [&](int tt) -> float {
                    return v0 * (0.375f * (G(-tt)      - G(-1 - tt))
                               + 0.125f * (G(1 - tt)   - G(-2 - tt)))
                         + vL * (0.125f * G(4094 - tt) + 0.375f * G(4095 - tt)
                               - 0.375f * G(4096 - tt) - 0.125f * G(4097 - tt));
                };
                int tt = 4 * q;
                a0 += corr(tt);
                a1 += corr(tt + 1);
                a2 += corr(tt + 2);
                a3 += corr(tt + 3);
            }
            reinterpret_cast<float4*>(s_flow)[q] = make_float4(a0, a1, a2, a3);
        }
    }

    // ---- 7. wait for the source row, then warp-gather from smem
    asm volatile("cp.async.wait_group 0;");
    __syncthreads();

    float* ob_base = out + (size_t)b * ROWN;
    #pragma unroll
    for (int w = 0; w < TLEN / NTHR; ++w) {
        int t = tid + NTHR * w;
        float fl = s_flow[t];

        // exact reference fp coordinate sequence
        float nl = (float)t + fl;
        float v  = 2.0f * (nl / (float)(TLEN - 1) - 0.5f);
        float ix = (v + 1.0f) * 0.5f;
        float iy = (v + 1.0f) * 0.5f * (float)(TLEN - 1);

        float xw = fminf(fminf(ix + 1.0f, 2.0f - ix), 1.0f);
        xw = fmaxf(xw, 0.0f);

        float y0 = floorf(iy);
        float fy = iy - y0;
        int y0i = (int)y0;
        int y1i = y0i + 1;
        float a0 = xw * (1.0f - fy) * ((y0i >= 0 && y0i < TLEN) ? 1.0f : 0.0f);
        float a1 = xw * fy         * ((y1i >= 0 && y1i < TLEN) ? 1.0f : 0.0f);
        int y0c = min(max(y0i, 0), TLEN - 1);
        int y1c = min(max(y1i, 0), TLEN - 1);

        float* ob = ob_base + t;
        #pragma unroll
        for (int c = 0; c < CH; ++c) {
            float g0 = s_src[c * TLEN + y0c];
            float g1 = s_src[c * TLEN + y1c];
            ob[c * TLEN] = a0 * g0 + a1 * g1;
        }
    }
}

// ---------------------------------------------------------------------------
extern "C" void kernel_launch(void* const* d_in, const int* in_sizes, int n_in,
                              void* d_out, int out_size) {
    const float* source    = (const float*)d_in[0];  // [512,12,4096]
    const float* flow_mag  = (const float*)d_in[1];  // [1]
    const float* noise     = (const float*)d_in[2];  // [512,1,4096]
    const float* smooth_k  = (const float*)d_in[3];  // [51]
    float*       out       = (float*)d_out;          // [512,12,4096]

    cudaFuncSetAttribute(k_fused, cudaFuncAttributeMaxDynamicSharedMemorySize,
                         SMEM_BYTES);
    k_fused<<<BATCH, NTHR, SMEM_BYTES>>>(source, noise, flow_mag, smooth_k, out);
}

// round 10
// speedup vs baseline: 1.0029x; 1.0029x over previous
#include <cuda_runtime.h>
#include <cuda_bf16.h>
#include <cstdint>

// Problem constants (from reference)
#define BATCH 512
#define CH    12
#define TLEN  4096
#define TD    1024     // TLEN / 4 (downsampled)
#define KS    51
#define STEPS 7
#define NTHR  256
#define ROWN  (CH * TLEN)          // 49152 floats per row

// ---------------------------------------------------------------------------
// Fully fused per-row kernel: one CTA owns one batch row.
//   phase A: L2-prefetch of this row's source (overlaps phase B)
//   phase B: downsample + VecInt(7) + polyphase 15-tap conv  -> smem flow
//   phase C: direct-global gather warp (R7 layout: lane == t), store out
// Small smem (~29 KB) keeps ~6 CTAs/SM resident so phase C has the same
// memory parallelism as the standalone R7 k_warp.
// ---------------------------------------------------------------------------
__global__ __launch_bounds__(NTHR)
void k_fused(const float* __restrict__ src,
             const float* __restrict__ noise,
             const float* __restrict__ flow_mag,
             const float* __restrict__ sker,
             float* __restrict__ out) {
    __shared__ float buf[2][TD];                 // integration ping-pong
    __shared__ float vec_pad[1044];              // [8 z][4*vec 1024][9 z]
    __shared__ float flow_s[TLEN];               // smoothed full-res flow
    __shared__ float ker_s[52];
    __shared__ __align__(16) float h4_s[16 * 4]; // h4_s[k*4+r] = h[r][k-7]

    const int b   = blockIdx.x;
    const int tid = threadIdx.x;
    const float mag = flow_mag[0];
    const float INV_TD1 = 1.0f / (float)(TD - 1);

    const float* srow = src + (size_t)b * ROWN;

    // ---- A. L2 prefetch of the whole source row (1536 lines, 6 per thread)
    {
        const char* base = (const char*)srow;
        #pragma unroll
        for (int k = 0; k < 6; ++k) {
            const char* p = base + (tid + NTHR * k) * 128;
            asm volatile("prefetch.global.L2 [%0];" :: "l"(p));
        }
    }

    // ---- B1. init: resize_linear(flow_field, 0.25) -> src = 4q+1.5,
    //          i0 = 4q+1, w = 0.5 ; resize_transform(<1): *0.25 ; VecInt /2^7
    float f[4];
    {
        const float* nrow = noise + (size_t)b * TLEN;
        #pragma unroll
        for (int j = 0; j < 4; ++j) {
            int q = tid + NTHR * j;
            float n0 = nrow[4 * q + 1];
            float n1 = nrow[4 * q + 2];
            float pf = 0.25f * ((mag * n0) * 0.5f + (mag * n1) * 0.5f);
            f[j] = pf * (1.0f / 128.0f);
            buf[0][q] = f[j];
        }
    }
    if (tid < 51) ker_s[tid] = sker[tid];
    if (tid < 8)  vec_pad[tid] = 0.0f;
    if (tid < 9)  vec_pad[1032 + tid] = 0.0f;
    __syncthreads();

    // ---- B2. composite polyphase kernel h[r][m], m = k-7 in [-7,8]
    //          flow[4q+r] = sum_m h[r][m] * (4*vec[q+m])   (interior)
    if (tid < 64) {
        const int r = tid >> 4;
        const int k = tid & 15;
        const int m = k - 7;
        const float W[4] = {0.625f, 0.875f, 0.125f, 0.375f};
        float acc = 0.0f;
        for (int j = -25; j <= 25; ++j) {
            int srp = r + j + 100;            // sr + 100, 100 % 4 == 0
            int p   = srp / 4 - 25;           // floor_div(sr, 4)
            int rho = srp & 3;
            int d   = (rho >= 2) ? 0 : -1;
            float w = W[rho];
            float g = ker_s[j + 25];
            int tgt = p + d;
            if (tgt == m)     acc += g * (1.0f - w);
            if (tgt + 1 == m) acc += g * w;
        }
        h4_s[k * 4 + r] = acc;
    }
    __syncthreads();

    // ---- B3. VecInt: 7 scaling-and-squaring warp steps (exact R8 fp sequence)
    int cur = 0;
    #pragma unroll
    for (int it = 0; it < STEPS; ++it) {
        #pragma unroll
        for (int j = 0; j < 4; ++j) {
            int q = tid + NTHR * j;
            float nl = (float)q + f[j];

            float ixn = nl * INV_TD1;
            float xw = fminf(fminf(ixn + 1.0f, 2.0f - ixn), 1.0f);
            xw = fmaxf(xw, 0.0f);

            float y0 = floorf(nl);
            float fy = nl - y0;
            int y0i = (int)y0;
            int y1i = y0i + 1;
            float m0 = (y0i >= 0 && y0i < TD) ? 1.0f : 0.0f;
            float m1 = (y1i >= 0 && y1i < TD) ? 1.0f : 0.0f;
            int y0c = min(max(y0i, 0), TD - 1);
            int y1c = min(max(y1i, 0), TD - 1);
            float g0 = buf[cur][y0c];
            float g1 = buf[cur][y1c];
            float warped = xw * ((1.0f - fy) * (m0 * g0) + fy * (m1 * g1));
            f[j] = f[j] + warped;
            buf[1 - cur][q] = f[j];
        }
        cur ^= 1;
        __syncthreads();
    }

    // ---- B4. publish scaled field (resize_transform >1: magnitude x4)
    #pragma unroll
    for (int j = 0; j < 4; ++j)
        vec_pad[8 + tid + NTHR * j] = 4.0f * f[j];
    __syncthreads();

    // ---- B5. 15-tap polyphase conv -> flow_s (full-res smoothed flow)
    {
        const float4* h4 = reinterpret_cast<const float4*>(h4_s);
        float v0 = vec_pad[8];
        float vL = vec_pad[8 + 1023];
        #pragma unroll
        for (int j = 0; j < 4; ++j) {
            int q = tid + NTHR * j;
            const float* wnd = vec_pad + q + 1;  // vec[q-7..q+8] (zero-padded)
            float a0 = 0.f, a1 = 0.f, a2 = 0.f, a3 = 0.f;
            #pragma unroll
            for (int k = 0; k < 16; ++k) {
                float wv = wnd[k];
                float4 hk = h4[k];
                a0 += hk.x * wv;
                a1 += hk.y * wv;
                a2 += hk.z * wv;
                a3 += hk.w * wv;
            }
            // Boundary corrections (R7 derivation): polyphase interior formula
            // with zero-padded vec differs from the reference's clamped
            // upsample + zero-padded conv at exactly 8 upsampled sites.
            if (q < 7 || q >= 1017) {
                auto G = [&](int jj) -> float {
                    return (jj >= -25 && jj <= 25) ? ker_s[jj + 25] : 0.0f;
                };
                auto corr = [&](int tt) -> float {
                    return v0 * (0.375f * (G(-tt)      - G(-1 - tt))
                               + 0.125f * (G(1 - tt)   - G(-2 - tt)))
                         + vL * (0.125f * G(4094 - tt) + 0.375f * G(4095 - tt)
                               - 0.375f * G(4096 - tt) - 0.125f * G(4097 - tt));
                };
                int tt = 4 * q;
                a0 += corr(tt);
                a1 += corr(tt + 1);
                a2 += corr(tt + 2);
                a3 += corr(tt + 3);
            }
            reinterpret_cast<float4*>(flow_s)[q] = make_float4(a0, a1, a2, a3);
        }
    }
    __syncthreads();

    // ---- C. warp-gather this row directly from global (R7 layout: lane==t)
    float* ob_base = out + (size_t)b * ROWN;
    #pragma unroll
    for (int w = 0; w < TLEN / NTHR; ++w) {
        int t = tid + NTHR * w;
        float fl = flow_s[t];

        // exact reference fp coordinate sequence
        float nl = (float)t + fl;
        float v  = 2.0f * (nl / (float)(TLEN - 1) - 0.5f);
        float ix = (v + 1.0f) * 0.5f;
        float iy = (v + 1.0f) * 0.5f * (float)(TLEN - 1);

        float xw = fminf(fminf(ix + 1.0f, 2.0f - ix), 1.0f);
        xw = fmaxf(xw, 0.0f);

        float y0 = floorf(iy);
        float fy = iy - y0;
        int y0i = (int)y0;
        int y1i = y0i + 1;
        float a0 = xw * (1.0f - fy) * ((y0i >= 0 && y0i < TLEN) ? 1.0f : 0.0f);
        float a1 = xw * fy         * ((y1i >= 0 && y1i < TLEN) ? 1.0f : 0.0f);
        int y0c = min(max(y0i, 0), TLEN - 1);
        int y1c = min(max(y1i, 0), TLEN - 1);

        // batch all gathers first for maximum MLP, then compute + store
        float g0v[CH], g1v[CH];
        #pragma unroll
        for (int c = 0; c < CH; ++c) {
            const float* sc = srow + c * TLEN;
            g0v[c] = __ldg(sc + y0c);
            g1v[c] = __ldg(sc + y1c);
        }
        float* ob = ob_base + t;
        #pragma unroll
        for (int c = 0; c < CH; ++c) {
            ob[c * TLEN] = a0 * g0v[c] + a1 * g1v[c];
        }
    }
}

// ---------------------------------------------------------------------------
extern "C" void kernel_launch(void* const* d_in, const int* in_sizes, int n_in,
                              void* d_out, int out_size) {
    const float* source    = (const float*)d_in[0];  // [512,12,4096]
    const float* flow_mag  = (const float*)d_in[1];  // [1]
    const float* noise     = (const float*)d_in[2];  // [512,1,4096]
    const float* smooth_k  = (const float*)d_in[3];  // [51]
    float*       out       = (float*)d_out;          // [512,12,4096]

    k_fused<<<BATCH, NTHR>>>(source, noise, flow_mag, smooth_k, out);
}